// round 6
// baseline (speedup 1.0000x reference)
#include <cuda_runtime.h>
#include <math.h>
#include <stdint.h>

#define NN 8192
#define DIM 256
#define NEG_SLOPE 0.2f
#define CAP 768            // max nnz per row (mean ~410, sd ~20)

// Scratch (device globals: no allocations allowed)
__device__ float g_h[NN * DIM];       // 8 MB, L2-resident during SpMM
__device__ float g_s1[NN];
__device__ float g_s2[NN];
__device__ int2  g_pairs[NN * CAP];   // interleaved {col, val_bits} CSR
__device__ int   g_nnz[NN];

__device__ __forceinline__ float lrelu(float x) {
    return x > 0.f ? x : NEG_SLOPE * x;
}

// ---------------------------------------------------------------------------
// K1: h = x @ W^T   (M=8192, N=256, K=256, fp32)
// ---------------------------------------------------------------------------
__global__ void gemm_xwt_kernel(const float* __restrict__ X,
                                const float* __restrict__ W) {
    __shared__ float As[16][64];
    __shared__ float Bs[16][64];

    const int bm = blockIdx.x * 64;
    const int bn = blockIdx.y * 64;
    const int tid = threadIdx.x;
    const int tm = (tid / 16) * 4;
    const int tn = (tid % 16) * 4;

    float acc[4][4] = {};

    const int lm = tid / 4;
    const int lk = (tid % 4) * 4;

    for (int k0 = 0; k0 < 256; k0 += 16) {
        float4 va = *(const float4*)&X[(size_t)(bm + lm) * 256 + k0 + lk];
        float4 vb = *(const float4*)&W[(size_t)(bn + lm) * 256 + k0 + lk];
        As[lk + 0][lm] = va.x; As[lk + 1][lm] = va.y;
        As[lk + 2][lm] = va.z; As[lk + 3][lm] = va.w;
        Bs[lk + 0][lm] = vb.x; Bs[lk + 1][lm] = vb.y;
        Bs[lk + 2][lm] = vb.z; Bs[lk + 3][lm] = vb.w;
        __syncthreads();

#pragma unroll
        for (int k = 0; k < 16; ++k) {
            float4 a4 = *(const float4*)&As[k][tm];
            float4 b4 = *(const float4*)&Bs[k][tn];
            float a[4] = {a4.x, a4.y, a4.z, a4.w};
            float b[4] = {b4.x, b4.y, b4.z, b4.w};
#pragma unroll
            for (int i = 0; i < 4; ++i)
#pragma unroll
                for (int j = 0; j < 4; ++j)
                    acc[i][j] = fmaf(a[i], b[j], acc[i][j]);
        }
        __syncthreads();
    }

#pragma unroll
    for (int i = 0; i < 4; ++i) {
        float4 v = {acc[i][0], acc[i][1], acc[i][2], acc[i][3]};
        *(float4*)&g_h[(size_t)(bm + tm + i) * 256 + bn + tn] = v;
    }
}

// ---------------------------------------------------------------------------
// K2: s1 = h @ a[:256], s2 = h @ a[256:]
// ---------------------------------------------------------------------------
__global__ void s_kernel(const float* __restrict__ a) {
    const int lane = threadIdx.x & 31;
    const int warp = threadIdx.x >> 5;
    const int row = blockIdx.x * 8 + warp;
    if (row >= NN) return;

    float p1 = 0.f, p2 = 0.f;
    for (int c = lane; c < 256; c += 32) {
        float hv = g_h[(size_t)row * 256 + c];
        p1 = fmaf(hv, __ldg(&a[c]), p1);
        p2 = fmaf(hv, __ldg(&a[256 + c]), p2);
    }
#pragma unroll
    for (int o = 16; o; o >>= 1) {
        p1 += __shfl_xor_sync(0xffffffffu, p1, o);
        p2 += __shfl_xor_sync(0xffffffffu, p2, o);
    }
    if (lane == 0) {
        g_s1[row] = p1;
        g_s2[row] = p2;
    }
}

// ---------------------------------------------------------------------------
// K3: one float4 pass over adj row i. Adj loads batched first (MLP=8), then
// mask + cached s2 gather, max, exps, Z, float4 G write + CSR emission.
// ---------------------------------------------------------------------------
__global__ void __launch_bounds__(256) softmax_g_kernel(const float* __restrict__ adj,
                                                        float* __restrict__ G) {
    const int i = blockIdx.x;
    const int t = threadIdx.x;
    const int lane = t & 31, warp = t >> 5;
    __shared__ float red[40];
    __shared__ int iscan[16];

    const float s1i = g_s1[i];
    const float4* arow = (const float4*)&adj[(size_t)i * NN];

    // batched adj loads: 8 independent LDG.128 up front
    float4 av4[8];
#pragma unroll
    for (int m = 0; m < 8; ++m) av4[m] = __ldcs(&arow[m * 256 + t]);

    // mask + s2 cache + max
    unsigned mask = 0;
    float mx = -3.0e38f;
    float ev[32];                       // pass1: s2 values; pass2: exps
#pragma unroll
    for (int m = 0; m < 8; ++m) {
        const int jb = (m * 256 + t) << 2;
        const float av[4] = {av4[m].x, av4[m].y, av4[m].z, av4[m].w};
#pragma unroll
        for (int c = 0; c < 4; ++c) {
            const int k = m * 4 + c;
            ev[k] = 0.f;
            if (av[c] != 0.f || (jb + c) == i) {
                mask |= (1u << k);
                const float s2v = g_s2[jb + c];
                ev[k] = s2v;
                mx = fmaxf(mx, s2v);
            }
        }
    }
#pragma unroll
    for (int o = 16; o; o >>= 1) mx = fmaxf(mx, __shfl_xor_sync(0xffffffffu, mx, o));
    if (lane == 0) red[warp] = mx;
    __syncthreads();
    if (warp == 0) {
        float v = (lane < 8) ? red[lane] : -3.0e38f;
#pragma unroll
        for (int o = 4; o; o >>= 1) v = fmaxf(v, __shfl_xor_sync(0xffffffffu, v, o));
        if (lane == 0) red[32] = lrelu(s1i + v);
    }
    __syncthreads();
    const float M = red[32];

    float sum = 0.f;
#pragma unroll
    for (int k = 0; k < 32; ++k) {
        float e = 0.f;
        if ((mask >> k) & 1u) {
            e = expf(lrelu(s1i + ev[k]) - M);
            sum += e;
        }
        ev[k] = e;
    }
#pragma unroll
    for (int o = 16; o; o >>= 1) sum += __shfl_xor_sync(0xffffffffu, sum, o);
    if (lane == 0) red[warp] = sum;
    __syncthreads();
    if (warp == 0) {
        float v = (lane < 8) ? red[lane] : 0.f;
#pragma unroll
        for (int o = 4; o; o >>= 1) v += __shfl_xor_sync(0xffffffffu, v, o);
        if (lane == 0) red[33] = 1.f / v;
    }
    __syncthreads();
    const float invZ = red[33];

    // dense G row write — float4 streaming stores
    float4* grow = (float4*)&G[(size_t)i * NN];
#pragma unroll
    for (int m = 0; m < 8; ++m) {
        float4 o = {ev[m * 4 + 0] * invZ, ev[m * 4 + 1] * invZ,
                    ev[m * 4 + 2] * invZ, ev[m * 4 + 3] * invZ};
        __stcs(&grow[m * 256 + t], o);
    }

    // ---- CSR compaction: block exclusive scan of per-thread popcounts ----
    const int cnt = __popc(mask);
    int incl = cnt;
#pragma unroll
    for (int o = 1; o < 32; o <<= 1) {
        int v = __shfl_up_sync(0xffffffffu, incl, o);
        if (lane >= o) incl += v;
    }
    if (lane == 31) iscan[warp] = incl;
    __syncthreads();
    if (warp == 0 && lane < 8) {
        int v = iscan[lane];
#pragma unroll
        for (int o = 1; o < 8; o <<= 1) {
            int u = __shfl_up_sync(0x000000ffu, v, o);
            if (lane >= o) v += u;
        }
        iscan[8 + lane] = v;
    }
    __syncthreads();
    const int excl = incl - cnt + (warp ? iscan[8 + warp - 1] : 0);
    if (t == 255) g_nnz[i] = excl + cnt;

    const size_t rb = (size_t)i * CAP;
    int off = excl;
#pragma unroll
    for (int k = 0; k < 32; ++k) {
        if ((mask >> k) & 1u) {
            const int col = (((k >> 2) * 256 + t) << 2) + (k & 3);
            g_pairs[rb + off] = make_int2(col, __float_as_int(ev[k] * invZ));
            ++off;
        }
    }
}

// ---------------------------------------------------------------------------
// K4: out = elu(G @ h). ONE WARP PER ROW (8 warps/block), 32 threads x 8 dims
// (2xfloat4). 32-pair chunks staged in per-warp smem with __syncwarp only
// (no block barrier, no cross-row padding). Register double-buffer of the
// next chunk; pairs consumed 2-at-a-time via int4 LDS.128.
// ---------------------------------------------------------------------------
__global__ void __launch_bounds__(256) spmm_elu_kernel(float* __restrict__ OUT) {
    const int w = threadIdx.x >> 5;        // warp = row slot 0..7
    const int l = threadIdx.x & 31;        // lane
    const int row = blockIdx.x * 8 + w;
    __shared__ int2 sp[8][32];             // 2 KB

    const int nnz = g_nnz[row];
    const size_t rb = (size_t)row * CAP;
    const int d0 = l * 8;

    float4 acc0 = {0.f, 0.f, 0.f, 0.f};
    float4 acc1 = {0.f, 0.f, 0.f, 0.f};

    // preload chunk 0
    int2 p = (l < nnz) ? __ldg(&g_pairs[rb + l]) : make_int2(row, 0);

    for (int base = 0; base < nnz; base += 32) {
        __syncwarp();
        sp[w][l] = p;
        __syncwarp();
        const int nidx = base + 32 + l;
        p = (nidx < nnz) ? __ldg(&g_pairs[rb + nidx]) : make_int2(row, 0);

#pragma unroll 4
        for (int j = 0; j < 32; j += 2) {
            const int4 q = *(const int4*)&sp[w][j];   // 2 pairs, one LDS.128
            const float4* h0 = (const float4*)&g_h[(size_t)q.x * 256 + d0];
            const float4* h1 = (const float4*)&g_h[(size_t)q.z * 256 + d0];
            const float4 a0 = h0[0], b0 = h0[1];
            const float4 a1 = h1[0], b1 = h1[1];
            const float v0 = __int_as_float(q.y);
            const float v1 = __int_as_float(q.w);
            acc0.x = fmaf(v0, a0.x, acc0.x); acc0.y = fmaf(v0, a0.y, acc0.y);
            acc0.z = fmaf(v0, a0.z, acc0.z); acc0.w = fmaf(v0, a0.w, acc0.w);
            acc1.x = fmaf(v0, b0.x, acc1.x); acc1.y = fmaf(v0, b0.y, acc1.y);
            acc1.z = fmaf(v0, b0.z, acc1.z); acc1.w = fmaf(v0, b0.w, acc1.w);
            acc0.x = fmaf(v1, a1.x, acc0.x); acc0.y = fmaf(v1, a1.y, acc0.y);
            acc0.z = fmaf(v1, a1.z, acc0.z); acc0.w = fmaf(v1, a1.w, acc0.w);
            acc1.x = fmaf(v1, b1.x, acc1.x); acc1.y = fmaf(v1, b1.y, acc1.y);
            acc1.z = fmaf(v1, b1.z, acc1.z); acc1.w = fmaf(v1, b1.w, acc1.w);
        }
    }

    float4 o0, o1;
    o0.x = acc0.x > 0.f ? acc0.x : expm1f(acc0.x);
    o0.y = acc0.y > 0.f ? acc0.y : expm1f(acc0.y);
    o0.z = acc0.z > 0.f ? acc0.z : expm1f(acc0.z);
    o0.w = acc0.w > 0.f ? acc0.w : expm1f(acc0.w);
    o1.x = acc1.x > 0.f ? acc1.x : expm1f(acc1.x);
    o1.y = acc1.y > 0.f ? acc1.y : expm1f(acc1.y);
    o1.z = acc1.z > 0.f ? acc1.z : expm1f(acc1.z);
    o1.w = acc1.w > 0.f ? acc1.w : expm1f(acc1.w);
    float4* orow = (float4*)&OUT[(size_t)row * 256 + d0];
    orow[0] = o0;
    orow[1] = o1;
}

// ---------------------------------------------------------------------------
extern "C" void kernel_launch(void* const* d_in, const int* in_sizes, int n_in,
                              void* d_out, int out_size) {
    const float* x   = (const float*)d_in[0];   // [8192, 256]
    const float* adj = (const float*)d_in[1];   // [8192, 8192]
    const float* W   = (const float*)d_in[2];   // [256, 256]
    const float* a   = (const float*)d_in[3];   // [512]

    float* out = (float*)d_out;                 // [8192, 256]
    float* G   = out + (size_t)NN * DIM;        // [8192, 8192]

    gemm_xwt_kernel<<<dim3(NN / 64, DIM / 64), 256>>>(x, W);
    s_kernel<<<NN / 8, 256>>>(a);
    softmax_g_kernel<<<NN, 256>>>(adj, G);
    spmm_elu_kernel<<<NN / 8, 256>>>(out);
}

// round 9
// speedup vs baseline: 1.2558x; 1.2558x over previous
#include <cuda_runtime.h>
#include <math.h>
#include <stdint.h>

#define NN 8192
#define DIM 256
#define NEG_SLOPE 0.2f
#define CAP 768            // max nnz per row (mean ~410, sd ~20)
#define CHUNK 64

// Scratch (device globals: no allocations allowed)
__device__ float g_h[NN * DIM];       // 8 MB, L2-resident during SpMM
__device__ float g_s1[NN];
__device__ float g_s2[NN];
__device__ int2  g_pairs[NN * CAP];   // interleaved {col, val_bits} CSR
__device__ int   g_nnz[NN];

__device__ __forceinline__ float lrelu(float x) {
    return x > 0.f ? x : NEG_SLOPE * x;
}

// ---------------------------------------------------------------------------
// K1: h = x @ W^T   (M=8192, N=256, K=256, fp32)
// ---------------------------------------------------------------------------
__global__ void gemm_xwt_kernel(const float* __restrict__ X,
                                const float* __restrict__ W) {
    __shared__ float As[16][64];
    __shared__ float Bs[16][64];

    const int bm = blockIdx.x * 64;
    const int bn = blockIdx.y * 64;
    const int tid = threadIdx.x;
    const int tm = (tid / 16) * 4;
    const int tn = (tid % 16) * 4;

    float acc[4][4] = {};

    const int lm = tid / 4;
    const int lk = (tid % 4) * 4;

    for (int k0 = 0; k0 < 256; k0 += 16) {
        float4 va = *(const float4*)&X[(size_t)(bm + lm) * 256 + k0 + lk];
        float4 vb = *(const float4*)&W[(size_t)(bn + lm) * 256 + k0 + lk];
        As[lk + 0][lm] = va.x; As[lk + 1][lm] = va.y;
        As[lk + 2][lm] = va.z; As[lk + 3][lm] = va.w;
        Bs[lk + 0][lm] = vb.x; Bs[lk + 1][lm] = vb.y;
        Bs[lk + 2][lm] = vb.z; Bs[lk + 3][lm] = vb.w;
        __syncthreads();

#pragma unroll
        for (int k = 0; k < 16; ++k) {
            float4 a4 = *(const float4*)&As[k][tm];
            float4 b4 = *(const float4*)&Bs[k][tn];
            float a[4] = {a4.x, a4.y, a4.z, a4.w};
            float b[4] = {b4.x, b4.y, b4.z, b4.w};
#pragma unroll
            for (int i = 0; i < 4; ++i)
#pragma unroll
                for (int j = 0; j < 4; ++j)
                    acc[i][j] = fmaf(a[i], b[j], acc[i][j]);
        }
        __syncthreads();
    }

#pragma unroll
    for (int i = 0; i < 4; ++i) {
        float4 v = {acc[i][0], acc[i][1], acc[i][2], acc[i][3]};
        *(float4*)&g_h[(size_t)(bm + tm + i) * 256 + bn + tn] = v;
    }
}

// ---------------------------------------------------------------------------
// K2: s1 = h @ a[:256], s2 = h @ a[256:]
// ---------------------------------------------------------------------------
__global__ void s_kernel(const float* __restrict__ a) {
    const int lane = threadIdx.x & 31;
    const int warp = threadIdx.x >> 5;
    const int row = blockIdx.x * 8 + warp;
    if (row >= NN) return;

    float p1 = 0.f, p2 = 0.f;
    for (int c = lane; c < 256; c += 32) {
        float hv = g_h[(size_t)row * 256 + c];
        p1 = fmaf(hv, __ldg(&a[c]), p1);
        p2 = fmaf(hv, __ldg(&a[256 + c]), p2);
    }
#pragma unroll
    for (int o = 16; o; o >>= 1) {
        p1 += __shfl_xor_sync(0xffffffffu, p1, o);
        p2 += __shfl_xor_sync(0xffffffffu, p2, o);
    }
    if (lane == 0) {
        g_s1[row] = p1;
        g_s2[row] = p2;
    }
}

// ---------------------------------------------------------------------------
// K3: one float4 pass over adj row i. Adj loads batched first (MLP=8), then
// mask + cached s2 gather, max, exps, Z, float4 G write + CSR emission.
// ---------------------------------------------------------------------------
__global__ void __launch_bounds__(256) softmax_g_kernel(const float* __restrict__ adj,
                                                        float* __restrict__ G) {
    const int i = blockIdx.x;
    const int t = threadIdx.x;
    const int lane = t & 31, warp = t >> 5;
    __shared__ float red[40];
    __shared__ int iscan[16];

    const float s1i = g_s1[i];
    const float4* arow = (const float4*)&adj[(size_t)i * NN];

    // batched adj loads: 8 independent LDG.128 up front
    float4 av4[8];
#pragma unroll
    for (int m = 0; m < 8; ++m) av4[m] = __ldcs(&arow[m * 256 + t]);

    // mask + s2 cache + max
    unsigned mask = 0;
    float mx = -3.0e38f;
    float ev[32];                       // pass1: s2 values; pass2: exps
#pragma unroll
    for (int m = 0; m < 8; ++m) {
        const int jb = (m * 256 + t) << 2;
        const float av[4] = {av4[m].x, av4[m].y, av4[m].z, av4[m].w};
#pragma unroll
        for (int c = 0; c < 4; ++c) {
            const int k = m * 4 + c;
            ev[k] = 0.f;
            if (av[c] != 0.f || (jb + c) == i) {
                mask |= (1u << k);
                const float s2v = g_s2[jb + c];
                ev[k] = s2v;
                mx = fmaxf(mx, s2v);
            }
        }
    }
#pragma unroll
    for (int o = 16; o; o >>= 1) mx = fmaxf(mx, __shfl_xor_sync(0xffffffffu, mx, o));
    if (lane == 0) red[warp] = mx;
    __syncthreads();
    if (warp == 0) {
        float v = (lane < 8) ? red[lane] : -3.0e38f;
#pragma unroll
        for (int o = 4; o; o >>= 1) v = fmaxf(v, __shfl_xor_sync(0xffffffffu, v, o));
        if (lane == 0) red[32] = lrelu(s1i + v);
    }
    __syncthreads();
    const float M = red[32];

    float sum = 0.f;
#pragma unroll
    for (int k = 0; k < 32; ++k) {
        float e = 0.f;
        if ((mask >> k) & 1u) {
            e = expf(lrelu(s1i + ev[k]) - M);
            sum += e;
        }
        ev[k] = e;
    }
#pragma unroll
    for (int o = 16; o; o >>= 1) sum += __shfl_xor_sync(0xffffffffu, sum, o);
    if (lane == 0) red[warp] = sum;
    __syncthreads();
    if (warp == 0) {
        float v = (lane < 8) ? red[lane] : 0.f;
#pragma unroll
        for (int o = 4; o; o >>= 1) v += __shfl_xor_sync(0xffffffffu, v, o);
        if (lane == 0) red[33] = 1.f / v;
    }
    __syncthreads();
    const float invZ = red[33];

    // dense G row write — float4 streaming stores
    float4* grow = (float4*)&G[(size_t)i * NN];
#pragma unroll
    for (int m = 0; m < 8; ++m) {
        float4 o = {ev[m * 4 + 0] * invZ, ev[m * 4 + 1] * invZ,
                    ev[m * 4 + 2] * invZ, ev[m * 4 + 3] * invZ};
        __stcs(&grow[m * 256 + t], o);
    }

    // ---- CSR compaction: block exclusive scan of per-thread popcounts ----
    const int cnt = __popc(mask);
    int incl = cnt;
#pragma unroll
    for (int o = 1; o < 32; o <<= 1) {
        int v = __shfl_up_sync(0xffffffffu, incl, o);
        if (lane >= o) incl += v;
    }
    if (lane == 31) iscan[warp] = incl;
    __syncthreads();
    if (warp == 0 && lane < 8) {
        int v = iscan[lane];
#pragma unroll
        for (int o = 1; o < 8; o <<= 1) {
            int u = __shfl_up_sync(0x000000ffu, v, o);
            if (lane >= o) v += u;
        }
        iscan[8 + lane] = v;
    }
    __syncthreads();
    const int excl = incl - cnt + (warp ? iscan[8 + warp - 1] : 0);
    if (t == 255) g_nnz[i] = excl + cnt;

    const size_t rb = (size_t)i * CAP;
    int off = excl;
#pragma unroll
    for (int k = 0; k < 32; ++k) {
        if ((mask >> k) & 1u) {
            const int col = (((k >> 2) * 256 + t) << 2) + (k & 3);
            g_pairs[rb + off] = make_int2(col, __float_as_int(ev[k] * invZ));
            ++off;
        }
    }
}

// ---------------------------------------------------------------------------
// K4: out = elu(G @ h). ROUND-3 proven structure: 4 rows/block, 64 thr/row,
// float4 (4 dims) per thread, simple smem staging (no register prefetch,
// keeps regs ~32 and occupancy ~86%). Single tweak vs r3: staged pairs
// consumed 2-at-a-time via int4 LDS.128 (halves LDS wavefronts).
// sp is force-aligned to 16B so the LDS.128 alignment is guaranteed.
// ---------------------------------------------------------------------------
__global__ void __launch_bounds__(256) spmm_elu_kernel(float* __restrict__ OUT) {
    const int g = threadIdx.x >> 6;        // row slot 0..3
    const int l = threadIdx.x & 63;        // dim quad 0..63
    const int row = blockIdx.x * 4 + g;
    __shared__ __align__(16) int2 sp[4][CHUNK];   // 512B per slot
    __shared__ int snnz[4];

    const int nnz = g_nnz[row];
    if (l == 0) snnz[g] = nnz;
    __syncthreads();
    const int mxnnz = max(max(snnz[0], snnz[1]), max(snnz[2], snnz[3]));

    const size_t rb = (size_t)row * CAP;
    float4 acc = {0.f, 0.f, 0.f, 0.f};

    for (int base = 0; base < mxnnz; base += CHUNK) {
        const int idx = base + l;
        const int2 p = (idx < nnz) ? __ldg(&g_pairs[rb + idx])
                                   : make_int2(row, 0);   // val=0, col in L1
        __syncthreads();
        sp[g][l] = p;
        __syncthreads();
#pragma unroll 8
        for (int j = 0; j < CHUNK; j += 2) {
            const int4 q = *(const int4*)&sp[g][j];       // 2 pairs, 1 LDS.128
            const float4 h0 = *(const float4*)&g_h[(size_t)q.x * 256 + 4 * l];
            const float4 h1 = *(const float4*)&g_h[(size_t)q.z * 256 + 4 * l];
            const float v0 = __int_as_float(q.y);
            const float v1 = __int_as_float(q.w);
            acc.x = fmaf(v0, h0.x, acc.x); acc.y = fmaf(v0, h0.y, acc.y);
            acc.z = fmaf(v0, h0.z, acc.z); acc.w = fmaf(v0, h0.w, acc.w);
            acc.x = fmaf(v1, h1.x, acc.x); acc.y = fmaf(v1, h1.y, acc.y);
            acc.z = fmaf(v1, h1.z, acc.z); acc.w = fmaf(v1, h1.w, acc.w);
        }
    }

    float4 o;
    o.x = acc.x > 0.f ? acc.x : expm1f(acc.x);
    o.y = acc.y > 0.f ? acc.y : expm1f(acc.y);
    o.z = acc.z > 0.f ? acc.z : expm1f(acc.z);
    o.w = acc.w > 0.f ? acc.w : expm1f(acc.w);
    *(float4*)&OUT[(size_t)row * 256 + 4 * l] = o;
}

// ---------------------------------------------------------------------------
extern "C" void kernel_launch(void* const* d_in, const int* in_sizes, int n_in,
                              void* d_out, int out_size) {
    const float* x   = (const float*)d_in[0];   // [8192, 256]
    const float* adj = (const float*)d_in[1];   // [8192, 8192]
    const float* W   = (const float*)d_in[2];   // [256, 256]
    const float* a   = (const float*)d_in[3];   // [512]

    float* out = (float*)d_out;                 // [8192, 256]
    float* G   = out + (size_t)NN * DIM;        // [8192, 8192]

    gemm_xwt_kernel<<<dim3(NN / 64, DIM / 64), 256>>>(x, W);
    s_kernel<<<NN / 8, 256>>>(a);
    softmax_g_kernel<<<NN, 256>>>(adj, G);
    spmm_elu_kernel<<<NN / 4, 256>>>(out);
}

// round 10
// speedup vs baseline: 1.2681x; 1.0097x over previous
#include <cuda_runtime.h>
#include <math.h>
#include <stdint.h>

#define NN 8192
#define DIM 256
#define NEG_SLOPE 0.2f
#define CAP 768            // max nnz per row (mean ~410, sd ~20)
#define CHUNK 64

// Scratch (device globals: no allocations allowed)
__device__ float g_h[NN * DIM];       // 8 MB, L2-resident during SpMM
__device__ float g_s1[NN];
__device__ float g_s2[NN];
__device__ int2  g_pairs[NN * CAP];   // interleaved {col, val_bits} CSR
__device__ int   g_nnz[NN];

__device__ __forceinline__ float lrelu(float x) {
    return x > 0.f ? x : NEG_SLOPE * x;
}

// ---------------------------------------------------------------------------
// K1: h = x @ W^T   (M=8192, N=256, K=256, fp32)
// ---------------------------------------------------------------------------
__global__ void gemm_xwt_kernel(const float* __restrict__ X,
                                const float* __restrict__ W) {
    __shared__ float As[16][64];
    __shared__ float Bs[16][64];

    const int bm = blockIdx.x * 64;
    const int bn = blockIdx.y * 64;
    const int tid = threadIdx.x;
    const int tm = (tid / 16) * 4;
    const int tn = (tid % 16) * 4;

    float acc[4][4] = {};

    const int lm = tid / 4;
    const int lk = (tid % 4) * 4;

    for (int k0 = 0; k0 < 256; k0 += 16) {
        float4 va = *(const float4*)&X[(size_t)(bm + lm) * 256 + k0 + lk];
        float4 vb = *(const float4*)&W[(size_t)(bn + lm) * 256 + k0 + lk];
        As[lk + 0][lm] = va.x; As[lk + 1][lm] = va.y;
        As[lk + 2][lm] = va.z; As[lk + 3][lm] = va.w;
        Bs[lk + 0][lm] = vb.x; Bs[lk + 1][lm] = vb.y;
        Bs[lk + 2][lm] = vb.z; Bs[lk + 3][lm] = vb.w;
        __syncthreads();

#pragma unroll
        for (int k = 0; k < 16; ++k) {
            float4 a4 = *(const float4*)&As[k][tm];
            float4 b4 = *(const float4*)&Bs[k][tn];
            float a[4] = {a4.x, a4.y, a4.z, a4.w};
            float b[4] = {b4.x, b4.y, b4.z, b4.w};
#pragma unroll
            for (int i = 0; i < 4; ++i)
#pragma unroll
                for (int j = 0; j < 4; ++j)
                    acc[i][j] = fmaf(a[i], b[j], acc[i][j]);
        }
        __syncthreads();
    }

#pragma unroll
    for (int i = 0; i < 4; ++i) {
        float4 v = {acc[i][0], acc[i][1], acc[i][2], acc[i][3]};
        *(float4*)&g_h[(size_t)(bm + tm + i) * 256 + bn + tn] = v;
    }
}

// ---------------------------------------------------------------------------
// K2: s1 = h @ a[:256], s2 = h @ a[256:]
// ---------------------------------------------------------------------------
__global__ void s_kernel(const float* __restrict__ a) {
    const int lane = threadIdx.x & 31;
    const int warp = threadIdx.x >> 5;
    const int row = blockIdx.x * 8 + warp;
    if (row >= NN) return;

    float p1 = 0.f, p2 = 0.f;
    for (int c = lane; c < 256; c += 32) {
        float hv = g_h[(size_t)row * 256 + c];
        p1 = fmaf(hv, __ldg(&a[c]), p1);
        p2 = fmaf(hv, __ldg(&a[256 + c]), p2);
    }
#pragma unroll
    for (int o = 16; o; o >>= 1) {
        p1 += __shfl_xor_sync(0xffffffffu, p1, o);
        p2 += __shfl_xor_sync(0xffffffffu, p2, o);
    }
    if (lane == 0) {
        g_s1[row] = p1;
        g_s2[row] = p2;
    }
}

// ---------------------------------------------------------------------------
// K3: one float4 pass over adj row i. Batched adj loads, cached s2, max,
// exps, Z, float4 G write. CSR pairs staged in smem then written COALESCED.
// ---------------------------------------------------------------------------
__global__ void __launch_bounds__(256) softmax_g_kernel(const float* __restrict__ adj,
                                                        float* __restrict__ G) {
    const int i = blockIdx.x;
    const int t = threadIdx.x;
    const int lane = t & 31, warp = t >> 5;
    __shared__ float red[40];
    __shared__ int iscan[16];
    __shared__ int stotal;
    __shared__ __align__(16) int2 spairs[CAP];   // 6 KB staging

    const float s1i = g_s1[i];
    const float4* arow = (const float4*)&adj[(size_t)i * NN];

    // batched adj loads: 8 independent LDG.128 up front
    float4 av4[8];
#pragma unroll
    for (int m = 0; m < 8; ++m) av4[m] = __ldcs(&arow[m * 256 + t]);

    // mask + s2 cache + max
    unsigned mask = 0;
    float mx = -3.0e38f;
    float ev[32];                       // pass1: s2 values; pass2: exps
#pragma unroll
    for (int m = 0; m < 8; ++m) {
        const int jb = (m * 256 + t) << 2;
        const float av[4] = {av4[m].x, av4[m].y, av4[m].z, av4[m].w};
#pragma unroll
        for (int c = 0; c < 4; ++c) {
            const int k = m * 4 + c;
            ev[k] = 0.f;
            if (av[c] != 0.f || (jb + c) == i) {
                mask |= (1u << k);
                const float s2v = g_s2[jb + c];
                ev[k] = s2v;
                mx = fmaxf(mx, s2v);
            }
        }
    }
#pragma unroll
    for (int o = 16; o; o >>= 1) mx = fmaxf(mx, __shfl_xor_sync(0xffffffffu, mx, o));
    if (lane == 0) red[warp] = mx;
    __syncthreads();
    if (warp == 0) {
        float v = (lane < 8) ? red[lane] : -3.0e38f;
#pragma unroll
        for (int o = 4; o; o >>= 1) v = fmaxf(v, __shfl_xor_sync(0xffffffffu, v, o));
        if (lane == 0) red[32] = lrelu(s1i + v);
    }
    __syncthreads();
    const float M = red[32];

    float sum = 0.f;
#pragma unroll
    for (int k = 0; k < 32; ++k) {
        float e = 0.f;
        if ((mask >> k) & 1u) {
            e = expf(lrelu(s1i + ev[k]) - M);
            sum += e;
        }
        ev[k] = e;
    }
#pragma unroll
    for (int o = 16; o; o >>= 1) sum += __shfl_xor_sync(0xffffffffu, sum, o);
    if (lane == 0) red[warp] = sum;
    __syncthreads();
    if (warp == 0) {
        float v = (lane < 8) ? red[lane] : 0.f;
#pragma unroll
        for (int o = 4; o; o >>= 1) v += __shfl_xor_sync(0xffffffffu, v, o);
        if (lane == 0) red[33] = 1.f / v;
    }
    __syncthreads();
    const float invZ = red[33];

    // dense G row write — float4 streaming stores
    float4* grow = (float4*)&G[(size_t)i * NN];
#pragma unroll
    for (int m = 0; m < 8; ++m) {
        float4 o = {ev[m * 4 + 0] * invZ, ev[m * 4 + 1] * invZ,
                    ev[m * 4 + 2] * invZ, ev[m * 4 + 3] * invZ};
        __stcs(&grow[m * 256 + t], o);
    }

    // ---- CSR compaction: block exclusive scan of per-thread popcounts ----
    const int cnt = __popc(mask);
    int incl = cnt;
#pragma unroll
    for (int o = 1; o < 32; o <<= 1) {
        int v = __shfl_up_sync(0xffffffffu, incl, o);
        if (lane >= o) incl += v;
    }
    if (lane == 31) iscan[warp] = incl;
    __syncthreads();
    if (warp == 0 && lane < 8) {
        int v = iscan[lane];
#pragma unroll
        for (int o = 1; o < 8; o <<= 1) {
            int u = __shfl_up_sync(0x000000ffu, v, o);
            if (lane >= o) v += u;
        }
        iscan[8 + lane] = v;
    }
    __syncthreads();
    const int excl = incl - cnt + (warp ? iscan[8 + warp - 1] : 0);
    if (t == 255) {
        const int tot = excl + cnt;
        g_nnz[i] = tot;
        stotal = tot;
    }

    // stage pairs into smem (scattered 8B smem stores — cheap), ...
    int off = excl;
#pragma unroll
    for (int k = 0; k < 32; ++k) {
        if ((mask >> k) & 1u) {
            const int col = (((k >> 2) * 256 + t) << 2) + (k & 3);
            spairs[off] = make_int2(col, __float_as_int(ev[k] * invZ));
            ++off;
        }
    }
    __syncthreads();

    // ... then write the row's CSR segment fully coalesced
    const int total = stotal;
    const size_t rb = (size_t)i * CAP;
    for (int idx = t; idx < total; idx += 256)
        __stcs(&g_pairs[rb + idx], spairs[idx]);
}

// ---------------------------------------------------------------------------
// K4: out = elu(G @ h). r9 structure (4 rows/block, 64 thr/row, float4 per
// thread, smem staging), single controlled change: consume 4 pairs per inner
// step (2x LDS.128 -> 4 independent LDG.128 -> 16 FMA) to double gather MLP.
// __launch_bounds__(256, 6) caps regs ~42 so occupancy stays >= 75%.
// ---------------------------------------------------------------------------
__global__ void __launch_bounds__(256, 6) spmm_elu_kernel(float* __restrict__ OUT) {
    const int g = threadIdx.x >> 6;        // row slot 0..3
    const int l = threadIdx.x & 63;        // dim quad 0..63
    const int row = blockIdx.x * 4 + g;
    __shared__ __align__(16) int2 sp[4][CHUNK];   // 512B per slot
    __shared__ int snnz[4];

    const int nnz = g_nnz[row];
    if (l == 0) snnz[g] = nnz;
    __syncthreads();
    const int mxnnz = max(max(snnz[0], snnz[1]), max(snnz[2], snnz[3]));

    const size_t rb = (size_t)row * CAP;
    float4 acc = {0.f, 0.f, 0.f, 0.f};

    for (int base = 0; base < mxnnz; base += CHUNK) {
        const int idx = base + l;
        const int2 p = (idx < nnz) ? __ldg(&g_pairs[rb + idx])
                                   : make_int2(row, 0);   // val=0, col in L1
        __syncthreads();
        sp[g][l] = p;
        __syncthreads();
#pragma unroll 4
        for (int j = 0; j < CHUNK; j += 4) {
            const int4 qa = *(const int4*)&sp[g][j];      // pairs j, j+1
            const int4 qb = *(const int4*)&sp[g][j + 2];  // pairs j+2, j+3
            const float4 h0 = *(const float4*)&g_h[(size_t)qa.x * 256 + 4 * l];
            const float4 h1 = *(const float4*)&g_h[(size_t)qa.z * 256 + 4 * l];
            const float4 h2 = *(const float4*)&g_h[(size_t)qb.x * 256 + 4 * l];
            const float4 h3 = *(const float4*)&g_h[(size_t)qb.z * 256 + 4 * l];
            const float v0 = __int_as_float(qa.y);
            const float v1 = __int_as_float(qa.w);
            const float v2 = __int_as_float(qb.y);
            const float v3 = __int_as_float(qb.w);
            acc.x = fmaf(v0, h0.x, acc.x); acc.y = fmaf(v0, h0.y, acc.y);
            acc.z = fmaf(v0, h0.z, acc.z); acc.w = fmaf(v0, h0.w, acc.w);
            acc.x = fmaf(v1, h1.x, acc.x); acc.y = fmaf(v1, h1.y, acc.y);
            acc.z = fmaf(v1, h1.z, acc.z); acc.w = fmaf(v1, h1.w, acc.w);
            acc.x = fmaf(v2, h2.x, acc.x); acc.y = fmaf(v2, h2.y, acc.y);
            acc.z = fmaf(v2, h2.z, acc.z); acc.w = fmaf(v2, h2.w, acc.w);
            acc.x = fmaf(v3, h3.x, acc.x); acc.y = fmaf(v3, h3.y, acc.y);
            acc.z = fmaf(v3, h3.z, acc.z); acc.w = fmaf(v3, h3.w, acc.w);
        }
    }

    float4 o;
    o.x = acc.x > 0.f ? acc.x : expm1f(acc.x);
    o.y = acc.y > 0.f ? acc.y : expm1f(acc.y);
    o.z = acc.z > 0.f ? acc.z : expm1f(acc.z);
    o.w = acc.w > 0.f ? acc.w : expm1f(acc.w);
    *(float4*)&OUT[(size_t)row * 256 + 4 * l] = o;
}

// ---------------------------------------------------------------------------
extern "C" void kernel_launch(void* const* d_in, const int* in_sizes, int n_in,
                              void* d_out, int out_size) {
    const float* x   = (const float*)d_in[0];   // [8192, 256]
    const float* adj = (const float*)d_in[1];   // [8192, 8192]
    const float* W   = (const float*)d_in[2];   // [256, 256]
    const float* a   = (const float*)d_in[3];   // [512]

    float* out = (float*)d_out;                 // [8192, 256]
    float* G   = out + (size_t)NN * DIM;        // [8192, 8192]

    gemm_xwt_kernel<<<dim3(NN / 64, DIM / 64), 256>>>(x, W);
    s_kernel<<<NN / 8, 256>>>(a);
    softmax_g_kernel<<<NN, 256>>>(adj, G);
    spmm_elu_kernel<<<NN / 4, 256>>>(out);
}

// round 12
// speedup vs baseline: 1.3481x; 1.0632x over previous
#include <cuda_runtime.h>
#include <math.h>
#include <stdint.h>

#define NN 8192
#define DIM 256
#define NEG_SLOPE 0.2f
#define CAP 768            // max nnz per row (mean ~410, sd ~20)
#define CHUNK 64

// Scratch (device globals: no allocations allowed)
__device__ float g_h[NN * DIM];       // 8 MB, L2-resident during SpMM
__device__ float g_s1[NN];
__device__ float g_s2[NN];
__device__ int2  g_pairs[NN * CAP];   // interleaved {col, val_bits} CSR
__device__ int   g_nnz[NN];

__device__ __forceinline__ float lrelu(float x) {
    return x > 0.f ? x : NEG_SLOPE * x;
}

// ---------------------------------------------------------------------------
// K1: h = x @ W^T   (M=8192, N=256, K=256, fp32)
// ---------------------------------------------------------------------------
__global__ void gemm_xwt_kernel(const float* __restrict__ X,
                                const float* __restrict__ W) {
    __shared__ float As[16][64];
    __shared__ float Bs[16][64];

    const int bm = blockIdx.x * 64;
    const int bn = blockIdx.y * 64;
    const int tid = threadIdx.x;
    const int tm = (tid / 16) * 4;
    const int tn = (tid % 16) * 4;

    float acc[4][4] = {};

    const int lm = tid / 4;
    const int lk = (tid % 4) * 4;

    for (int k0 = 0; k0 < 256; k0 += 16) {
        float4 va = *(const float4*)&X[(size_t)(bm + lm) * 256 + k0 + lk];
        float4 vb = *(const float4*)&W[(size_t)(bn + lm) * 256 + k0 + lk];
        As[lk + 0][lm] = va.x; As[lk + 1][lm] = va.y;
        As[lk + 2][lm] = va.z; As[lk + 3][lm] = va.w;
        Bs[lk + 0][lm] = vb.x; Bs[lk + 1][lm] = vb.y;
        Bs[lk + 2][lm] = vb.z; Bs[lk + 3][lm] = vb.w;
        __syncthreads();

#pragma unroll
        for (int k = 0; k < 16; ++k) {
            float4 a4 = *(const float4*)&As[k][tm];
            float4 b4 = *(const float4*)&Bs[k][tn];
            float a[4] = {a4.x, a4.y, a4.z, a4.w};
            float b[4] = {b4.x, b4.y, b4.z, b4.w};
#pragma unroll
            for (int i = 0; i < 4; ++i)
#pragma unroll
                for (int j = 0; j < 4; ++j)
                    acc[i][j] = fmaf(a[i], b[j], acc[i][j]);
        }
        __syncthreads();
    }

#pragma unroll
    for (int i = 0; i < 4; ++i) {
        float4 v = {acc[i][0], acc[i][1], acc[i][2], acc[i][3]};
        *(float4*)&g_h[(size_t)(bm + tm + i) * 256 + bn + tn] = v;
    }
}

// ---------------------------------------------------------------------------
// K2: s1 = h @ a[:256], s2 = h @ a[256:]
// ---------------------------------------------------------------------------
__global__ void s_kernel(const float* __restrict__ a) {
    const int lane = threadIdx.x & 31;
    const int warp = threadIdx.x >> 5;
    const int row = blockIdx.x * 8 + warp;
    if (row >= NN) return;

    float p1 = 0.f, p2 = 0.f;
    for (int c = lane; c < 256; c += 32) {
        float hv = g_h[(size_t)row * 256 + c];
        p1 = fmaf(hv, __ldg(&a[c]), p1);
        p2 = fmaf(hv, __ldg(&a[256 + c]), p2);
    }
#pragma unroll
    for (int o = 16; o; o >>= 1) {
        p1 += __shfl_xor_sync(0xffffffffu, p1, o);
        p2 += __shfl_xor_sync(0xffffffffu, p2, o);
    }
    if (lane == 0) {
        g_s1[row] = p1;
        g_s2[row] = p2;
    }
}

// ---------------------------------------------------------------------------
// K3: one float4 pass over adj row i. Key change: s2 is loaded with
// COALESCED float4 loads (thread t's 32 columns are the contiguous quads
// 4*(m*256+t)..+3), killing the scattered conditional gather. CSR pairs
// staged in smem then written coalesced.
// ---------------------------------------------------------------------------
__global__ void __launch_bounds__(256) softmax_g_kernel(const float* __restrict__ adj,
                                                        float* __restrict__ G) {
    const int i = blockIdx.x;
    const int t = threadIdx.x;
    const int lane = t & 31, warp = t >> 5;
    __shared__ float red[40];
    __shared__ int iscan[16];
    __shared__ int stotal;
    __shared__ __align__(16) int2 spairs[CAP];   // 6 KB staging

    const float s1i = g_s1[i];
    const float4* arow = (const float4*)&adj[(size_t)i * NN];
    const float4* s2v4 = (const float4*)g_s2;

    // batched adj loads: 8 independent LDG.128 up front
    float4 av4[8];
#pragma unroll
    for (int m = 0; m < 8; ++m) av4[m] = __ldcs(&arow[m * 256 + t]);

    // mask + coalesced s2 load + max
    unsigned mask = 0;
    float mx = -3.0e38f;
    float ev[32];                       // pass1: s2 values; pass2: exps
#pragma unroll
    for (int m = 0; m < 8; ++m) {
        const float4 sv = __ldg(&s2v4[m * 256 + t]);   // coalesced, L2-resident
        const int jb = (m * 256 + t) << 2;
        const float av[4] = {av4[m].x, av4[m].y, av4[m].z, av4[m].w};
        const float s2a[4] = {sv.x, sv.y, sv.z, sv.w};
#pragma unroll
        for (int c = 0; c < 4; ++c) {
            const int k = m * 4 + c;
            ev[k] = s2a[c];
            if (av[c] != 0.f || (jb + c) == i) {
                mask |= (1u << k);
                mx = fmaxf(mx, s2a[c]);
            }
        }
    }
#pragma unroll
    for (int o = 16; o; o >>= 1) mx = fmaxf(mx, __shfl_xor_sync(0xffffffffu, mx, o));
    if (lane == 0) red[warp] = mx;
    __syncthreads();
    if (warp == 0) {
        float v = (lane < 8) ? red[lane] : -3.0e38f;
#pragma unroll
        for (int o = 4; o; o >>= 1) v = fmaxf(v, __shfl_xor_sync(0xffffffffu, v, o));
        if (lane == 0) red[32] = lrelu(s1i + v);
    }
    __syncthreads();
    const float M = red[32];

    float sum = 0.f;
#pragma unroll
    for (int k = 0; k < 32; ++k) {
        float e = 0.f;
        if ((mask >> k) & 1u) {
            e = expf(lrelu(s1i + ev[k]) - M);
            sum += e;
        }
        ev[k] = e;
    }
#pragma unroll
    for (int o = 16; o; o >>= 1) sum += __shfl_xor_sync(0xffffffffu, sum, o);
    if (lane == 0) red[warp] = sum;
    __syncthreads();
    if (warp == 0) {
        float v = (lane < 8) ? red[lane] : 0.f;
#pragma unroll
        for (int o = 4; o; o >>= 1) v += __shfl_xor_sync(0xffffffffu, v, o);
        if (lane == 0) red[33] = 1.f / v;
    }
    __syncthreads();
    const float invZ = red[33];

    // dense G row write — float4 streaming stores
    float4* grow = (float4*)&G[(size_t)i * NN];
#pragma unroll
    for (int m = 0; m < 8; ++m) {
        float4 o = {ev[m * 4 + 0] * invZ, ev[m * 4 + 1] * invZ,
                    ev[m * 4 + 2] * invZ, ev[m * 4 + 3] * invZ};
        __stcs(&grow[m * 256 + t], o);
    }

    // ---- CSR compaction: block exclusive scan of per-thread popcounts ----
    const int cnt = __popc(mask);
    int incl = cnt;
#pragma unroll
    for (int o = 1; o < 32; o <<= 1) {
        int v = __shfl_up_sync(0xffffffffu, incl, o);
        if (lane >= o) incl += v;
    }
    if (lane == 31) iscan[warp] = incl;
    __syncthreads();
    if (warp == 0 && lane < 8) {
        int v = iscan[lane];
#pragma unroll
        for (int o = 1; o < 8; o <<= 1) {
            int u = __shfl_up_sync(0x000000ffu, v, o);
            if (lane >= o) v += u;
        }
        iscan[8 + lane] = v;
    }
    __syncthreads();
    const int excl = incl - cnt + (warp ? iscan[8 + warp - 1] : 0);
    if (t == 255) {
        const int tot = excl + cnt;
        g_nnz[i] = tot;
        stotal = tot;
    }

    // stage pairs into smem (scattered 8B smem stores — cheap), ...
    int off = excl;
#pragma unroll
    for (int k = 0; k < 32; ++k) {
        if ((mask >> k) & 1u) {
            const int col = (((k >> 2) * 256 + t) << 2) + (k & 3);
            spairs[off] = make_int2(col, __float_as_int(ev[k] * invZ));
            ++off;
        }
    }
    __syncthreads();

    // ... then write the row's CSR segment fully coalesced
    const int total = stotal;
    const size_t rb = (size_t)i * CAP;
    for (int idx = t; idx < total; idx += 256)
        __stcs(&g_pairs[rb + idx], spairs[idx]);
}

// ---------------------------------------------------------------------------
// K4: out = elu(G @ h). r9-EXACT proven config (182us, regs 32, occ 86%):
// 4 rows/block, 64 thr/row, float4/thread, smem staging, pairs consumed
// 2-at-a-time via int4 LDS.128. No launch_bounds minBlocks, no MLP-4.
// ---------------------------------------------------------------------------
__global__ void __launch_bounds__(256) spmm_elu_kernel(float* __restrict__ OUT) {
    const int g = threadIdx.x >> 6;        // row slot 0..3
    const int l = threadIdx.x & 63;        // dim quad 0..63
    const int row = blockIdx.x * 4 + g;
    __shared__ __align__(16) int2 sp[4][CHUNK];   // 512B per slot
    __shared__ int snnz[4];

    const int nnz = g_nnz[row];
    if (l == 0) snnz[g] = nnz;
    __syncthreads();
    const int mxnnz = max(max(snnz[0], snnz[1]), max(snnz[2], snnz[3]));

    const size_t rb = (size_t)row * CAP;
    float4 acc = {0.f, 0.f, 0.f, 0.f};

    for (int base = 0; base < mxnnz; base += CHUNK) {
        const int idx = base + l;
        const int2 p = (idx < nnz) ? __ldg(&g_pairs[rb + idx])
                                   : make_int2(row, 0);   // val=0, col in L1
        __syncthreads();
        sp[g][l] = p;
        __syncthreads();
#pragma unroll 8
        for (int j = 0; j < CHUNK; j += 2) {
            const int4 q = *(const int4*)&sp[g][j];       // 2 pairs, 1 LDS.128
            const float4 h0 = *(const float4*)&g_h[(size_t)q.x * 256 + 4 * l];
            const float4 h1 = *(const float4*)&g_h[(size_t)q.z * 256 + 4 * l];
            const float v0 = __int_as_float(q.y);
            const float v1 = __int_as_float(q.w);
            acc.x = fmaf(v0, h0.x, acc.x); acc.y = fmaf(v0, h0.y, acc.y);
            acc.z = fmaf(v0, h0.z, acc.z); acc.w = fmaf(v0, h0.w, acc.w);
            acc.x = fmaf(v1, h1.x, acc.x); acc.y = fmaf(v1, h1.y, acc.y);
            acc.z = fmaf(v1, h1.z, acc.z); acc.w = fmaf(v1, h1.w, acc.w);
        }
    }

    float4 o;
    o.x = acc.x > 0.f ? acc.x : expm1f(acc.x);
    o.y = acc.y > 0.f ? acc.y : expm1f(acc.y);
    o.z = acc.z > 0.f ? acc.z : expm1f(acc.z);
    o.w = acc.w > 0.f ? acc.w : expm1f(acc.w);
    *(float4*)&OUT[(size_t)row * 256 + 4 * l] = o;
}

// ---------------------------------------------------------------------------
extern "C" void kernel_launch(void* const* d_in, const int* in_sizes, int n_in,
                              void* d_out, int out_size) {
    const float* x   = (const float*)d_in[0];   // [8192, 256]
    const float* adj = (const float*)d_in[1];   // [8192, 8192]
    const float* W   = (const float*)d_in[2];   // [256, 256]
    const float* a   = (const float*)d_in[3];   // [512]

    float* out = (float*)d_out;                 // [8192, 256]
    float* G   = out + (size_t)NN * DIM;        // [8192, 8192]

    gemm_xwt_kernel<<<dim3(NN / 64, DIM / 64), 256>>>(x, W);
    s_kernel<<<NN / 8, 256>>>(a);
    softmax_g_kernel<<<NN, 256>>>(adj, G);
    spmm_elu_kernel<<<NN / 4, 256>>>(out);
}